// round 4
// baseline (speedup 1.0000x reference)
#include <cuda_runtime.h>
#include <math.h>

#define N_NODES 128
#define F_DIM   128
#define H_DIM   64
#define C_OUT   40
#define BATCH   4096

// Padded stride for conflict-free float4 smem access (132 % 32 == 4)
#define A2_STRIDE 132
#define X_STRIDE  132
#define Y_STRIDE  68

__device__ __align__(16) float g_Anorm[N_NODES * N_NODES];
__device__ __align__(16) float g_A2[N_NODES * A2_STRIDE];   // padded, A2 is symmetric

typedef unsigned long long u64;

__device__ __forceinline__ u64 pk2(float a, float b) {
    u64 r; asm("mov.b64 %0, {%1, %2};" : "=l"(r) : "f"(a), "f"(b)); return r;
}
__device__ __forceinline__ u64 ffma2(u64 a, u64 b, u64 c) {
    u64 d; asm("fma.rn.f32x2 %0, %1, %2, %3;" : "=l"(d) : "l"(a), "l"(b), "l"(c)); return d;
}
__device__ __forceinline__ float2 up2(u64 v) {
    float lo, hi; asm("mov.b64 {%0, %1}, %2;" : "=f"(lo), "=f"(hi) : "l"(v));
    return make_float2(lo, hi);
}

// ---------------------------------------------------------------------------
// Kernel 1: build normalized adjacency A_norm = D^-1/2 (A_sym + I) D^-1/2
// from tril-parameterized edge weights. 1 block, 128 threads (row per thread).
// ---------------------------------------------------------------------------
__global__ void build_Anorm(const float* __restrict__ edge_w) {
    __shared__ float dinv[N_NODES];
    int i = threadIdx.x;
    float d = 0.f;
    for (int j = 0; j < N_NODES; j++) {
        int a = i > j ? i : j;
        int b = i > j ? j : i;
        float v = edge_w[(a * (a + 1)) / 2 + b];   // tril row-major index
        if (i == j) v += 1.0f;                     // add self loop
        g_Anorm[i * N_NODES + j] = v;
        d += v;
    }
    dinv[i] = (d > 0.f) ? (1.0f / sqrtf(d)) : 0.0f;
    __syncthreads();
    float di = dinv[i];
    for (int j = 0; j < N_NODES; j++)
        g_Anorm[i * N_NODES + j] *= di * dinv[j];
}

// ---------------------------------------------------------------------------
// Kernel 2: A2 = A_norm @ A_norm  (symmetric). 128 blocks, 128 threads.
// Stored with padded row stride 132 (pad zeroed) for direct float4 smem copy.
// ---------------------------------------------------------------------------
__global__ void build_A2() {
    __shared__ float rowi[N_NODES];
    int i = blockIdx.x, j = threadIdx.x;
    rowi[j] = g_Anorm[i * N_NODES + j];
    __syncthreads();
    float s = 0.f;
    for (int k = 0; k < N_NODES; k++)
        s = fmaf(rowi[k], g_Anorm[k * N_NODES + j], s);
    g_A2[i * A2_STRIDE + j] = s;
    if (j < A2_STRIDE - N_NODES) g_A2[i * A2_STRIDE + N_NODES + j] = 0.f;
}

// ---------------------------------------------------------------------------
// Kernel 3: fused per-batch pipeline. One batch per CTA, 256 threads.
//   Y = X @ W            (128x128 @ 128x64)
//   Z = A2 @ Y           (128x128 @ 128x64)
//   h = relu(Z + lin_b)
//   pooled = relu(conv_w^T h + conv_b)
//   out = pooled @ fc_w + fc_b
// Thread (ty,tx): ty=tid>>3 (32 row-tiles of 4 nodes), tx=tid&7 (8 col-tiles
// of 8 hiddens). Accumulators are 16 packed f32x2 (4 rows x 4 col-pairs).
// ---------------------------------------------------------------------------
__global__ void __launch_bounds__(256, 1) fused_kernel(
    const float* __restrict__ x,
    const float* __restrict__ lin_w, const float* __restrict__ lin_b,
    const float* __restrict__ conv_w, const float* __restrict__ conv_b,
    const float* __restrict__ fc_w, const float* __restrict__ fc_b,
    float* __restrict__ out)
{
    extern __shared__ float sm[];
    float* Xt  = sm;                          // [128][132]  Xt[f][n] (transposed)
    float* A2s = Xt + F_DIM * X_STRIDE;       // [128][132]  A2s[j][n] (symmetric)
    float* Ws  = A2s + N_NODES * A2_STRIDE;   // [128][64]
    float* Ys  = Ws + F_DIM * H_DIM;          // [128][68]
    float* pooledS = Ys + N_NODES * Y_STRIDE; // [64]

    const int tid = threadIdx.x;
    const int tx = tid & 7;    // h columns 8*tx .. 8*tx+7
    const int ty = tid >> 3;   // n rows    4*ty .. 4*ty+3
    const int b = blockIdx.x;

    if (tid < H_DIM) pooledS[tid] = conv_b[0];

    // --- load W (flat copy) ---
    {
        const float4* W4 = (const float4*)lin_w;
        float4* Ws4 = (float4*)Ws;
        for (int idx = tid; idx < F_DIM * H_DIM / 4; idx += 256) Ws4[idx] = W4[idx];
    }
    // --- load A2 (flat copy, already padded) ---
    {
        const float4* A24 = (const float4*)g_A2;
        float4* A2s4 = (float4*)A2s;
        for (int idx = tid; idx < N_NODES * A2_STRIDE / 4; idx += 256) A2s4[idx] = A24[idx];
    }
    // --- load X transposed: Xt[f][n] = X[n][f]. Lane index maps to n so the
    //     4 scalar smem stores per float4 are bank-conflict-free. ---
    {
        const float4* X4 = (const float4*)(x + (size_t)b * N_NODES * F_DIM);
        for (int idx = tid; idx < N_NODES * F_DIM / 4; idx += 256) {
            int l = idx & 31;
            int g = idx >> 5;
            int n = ((g & 3) << 5) | l;
            int f4 = g >> 2;
            float4 v = X4[n * (F_DIM / 4) + f4];
            int f = f4 * 4;
            Xt[(f + 0) * X_STRIDE + n] = v.x;
            Xt[(f + 1) * X_STRIDE + n] = v.y;
            Xt[(f + 2) * X_STRIDE + n] = v.z;
            Xt[(f + 3) * X_STRIDE + n] = v.w;
        }
    }
    __syncthreads();

    u64 acc[4][4];
#pragma unroll
    for (int i = 0; i < 4; i++)
#pragma unroll
        for (int p = 0; p < 4; p++) acc[i][p] = 0ull;

    // ---------------- GEMM1: Y = X @ W ----------------
#pragma unroll 4
    for (int f = 0; f < F_DIM; f++) {
        float4 xv = *(const float4*)(Xt + f * X_STRIDE + 4 * ty);
        float4 w0 = *(const float4*)(Ws + f * H_DIM + 8 * tx);
        float4 w1 = *(const float4*)(Ws + f * H_DIM + 8 * tx + 4);
        u64 b0 = pk2(w0.x, w0.y), b1 = pk2(w0.z, w0.w);
        u64 b2 = pk2(w1.x, w1.y), b3 = pk2(w1.z, w1.w);
        u64 a0 = pk2(xv.x, xv.x), a1 = pk2(xv.y, xv.y);
        u64 a2 = pk2(xv.z, xv.z), a3 = pk2(xv.w, xv.w);
        acc[0][0]=ffma2(a0,b0,acc[0][0]); acc[0][1]=ffma2(a0,b1,acc[0][1]);
        acc[0][2]=ffma2(a0,b2,acc[0][2]); acc[0][3]=ffma2(a0,b3,acc[0][3]);
        acc[1][0]=ffma2(a1,b0,acc[1][0]); acc[1][1]=ffma2(a1,b1,acc[1][1]);
        acc[1][2]=ffma2(a1,b2,acc[1][2]); acc[1][3]=ffma2(a1,b3,acc[1][3]);
        acc[2][0]=ffma2(a2,b0,acc[2][0]); acc[2][1]=ffma2(a2,b1,acc[2][1]);
        acc[2][2]=ffma2(a2,b2,acc[2][2]); acc[2][3]=ffma2(a2,b3,acc[2][3]);
        acc[3][0]=ffma2(a3,b0,acc[3][0]); acc[3][1]=ffma2(a3,b1,acc[3][1]);
        acc[3][2]=ffma2(a3,b2,acc[3][2]); acc[3][3]=ffma2(a3,b3,acc[3][3]);
    }

    // store Y tile
#pragma unroll
    for (int i = 0; i < 4; i++) {
        int n = 4 * ty + i;
        float2 z0 = up2(acc[i][0]), z1 = up2(acc[i][1]);
        float2 z2 = up2(acc[i][2]), z3 = up2(acc[i][3]);
        *(float4*)(Ys + n * Y_STRIDE + 8 * tx)     = make_float4(z0.x, z0.y, z1.x, z1.y);
        *(float4*)(Ys + n * Y_STRIDE + 8 * tx + 4) = make_float4(z2.x, z2.y, z3.x, z3.y);
    }
    __syncthreads();

#pragma unroll
    for (int i = 0; i < 4; i++)
#pragma unroll
        for (int p = 0; p < 4; p++) acc[i][p] = 0ull;

    // ---------------- GEMM2: Z = A2 @ Y ----------------
    // A2 symmetric: A2s[j][n] == A2[n][j], so the float4 over n works directly.
#pragma unroll 4
    for (int j = 0; j < N_NODES; j++) {
        float4 av = *(const float4*)(A2s + j * A2_STRIDE + 4 * ty);
        float4 y0 = *(const float4*)(Ys + j * Y_STRIDE + 8 * tx);
        float4 y1 = *(const float4*)(Ys + j * Y_STRIDE + 8 * tx + 4);
        u64 b0 = pk2(y0.x, y0.y), b1 = pk2(y0.z, y0.w);
        u64 b2 = pk2(y1.x, y1.y), b3 = pk2(y1.z, y1.w);
        u64 a0 = pk2(av.x, av.x), a1 = pk2(av.y, av.y);
        u64 a2 = pk2(av.z, av.z), a3 = pk2(av.w, av.w);
        acc[0][0]=ffma2(a0,b0,acc[0][0]); acc[0][1]=ffma2(a0,b1,acc[0][1]);
        acc[0][2]=ffma2(a0,b2,acc[0][2]); acc[0][3]=ffma2(a0,b3,acc[0][3]);
        acc[1][0]=ffma2(a1,b0,acc[1][0]); acc[1][1]=ffma2(a1,b1,acc[1][1]);
        acc[1][2]=ffma2(a1,b2,acc[1][2]); acc[1][3]=ffma2(a1,b3,acc[1][3]);
        acc[2][0]=ffma2(a2,b0,acc[2][0]); acc[2][1]=ffma2(a2,b1,acc[2][1]);
        acc[2][2]=ffma2(a2,b2,acc[2][2]); acc[2][3]=ffma2(a2,b3,acc[2][3]);
        acc[3][0]=ffma2(a3,b0,acc[3][0]); acc[3][1]=ffma2(a3,b1,acc[3][1]);
        acc[3][2]=ffma2(a3,b2,acc[3][2]); acc[3][3]=ffma2(a3,b3,acc[3][3]);
    }

    // ---------------- epilogue: bias + relu + conv pool ----------------
    float lb[8];
    {
        float4 l0 = *(const float4*)(lin_b + 8 * tx);
        float4 l1 = *(const float4*)(lin_b + 8 * tx + 4);
        lb[0]=l0.x; lb[1]=l0.y; lb[2]=l0.z; lb[3]=l0.w;
        lb[4]=l1.x; lb[5]=l1.y; lb[6]=l1.z; lb[7]=l1.w;
    }
    float pool[8] = {0,0,0,0,0,0,0,0};
#pragma unroll
    for (int i = 0; i < 4; i++) {
        float cw = conv_w[4 * ty + i];
#pragma unroll
        for (int p = 0; p < 4; p++) {
            float2 z = up2(acc[i][p]);
            pool[2*p]   = fmaf(fmaxf(z.x + lb[2*p],   0.f), cw, pool[2*p]);
            pool[2*p+1] = fmaf(fmaxf(z.y + lb[2*p+1], 0.f), cw, pool[2*p+1]);
        }
    }
#pragma unroll
    for (int jj = 0; jj < 8; jj++)
        atomicAdd(&pooledS[8 * tx + jj], pool[jj]);
    __syncthreads();

    // ---------------- final fc: out[b] = relu(pooled) @ fc_w + fc_b ----------------
    if (tid < C_OUT) {
        float s = fc_b[tid];
#pragma unroll 8
        for (int h = 0; h < H_DIM; h++)
            s = fmaf(fmaxf(pooledS[h], 0.f), fc_w[h * C_OUT + tid], s);
        out[b * C_OUT + tid] = s;
    }
}

// ---------------------------------------------------------------------------
extern "C" void kernel_launch(void* const* d_in, const int* in_sizes, int n_in,
                              void* d_out, int out_size) {
    const float* x      = (const float*)d_in[0];
    const float* edge_w = (const float*)d_in[1];
    const float* lin_w  = (const float*)d_in[2];
    const float* lin_b  = (const float*)d_in[3];
    const float* conv_w = (const float*)d_in[4];
    const float* conv_b = (const float*)d_in[5];
    const float* fc_w   = (const float*)d_in[6];
    const float* fc_b   = (const float*)d_in[7];
    float* out = (float*)d_out;

    const int smem_bytes =
        (F_DIM * X_STRIDE + N_NODES * A2_STRIDE + F_DIM * H_DIM +
         N_NODES * Y_STRIDE + H_DIM) * (int)sizeof(float);   // 203,264 B

    cudaFuncSetAttribute(fused_kernel,
                         cudaFuncAttributeMaxDynamicSharedMemorySize, smem_bytes);

    build_Anorm<<<1, 128>>>(edge_w);
    build_A2<<<N_NODES, 128>>>();
    fused_kernel<<<BATCH, 256, smem_bytes>>>(x, lin_w, lin_b, conv_w, conv_b,
                                             fc_w, fc_b, out);
}